// round 12
// baseline (speedup 1.0000x reference)
#include <cuda_runtime.h>
#include <math.h>

#define N 8192
#define D 1024

// Scratch (allocation-free rule: __device__ globals)
__device__ float g_a[N];            // sigmoid(x @ w)
__device__ int4  g_pack[N];         // {idx, bits(m), bits(c), 0} per column
__device__ int   g_rowstart[N + 2]; // lower_bound(idx >= j), j in [0, N+1]

// ---------------------------------------------------------------------------
// Kernel 1: z = x @ w, a = sigmoid(z).  One warp per row. NEW: 8 register-
// free L1 prefetches fire before the (unchanged) load-FFMA chain — ptxas
// cannot interleave consumers into them, so 8 requests are genuinely in
// flight. Values and FFMA order unchanged -> g_a bitwise identical.
// ---------------------------------------------------------------------------
__global__ void __launch_bounds__(256) k_logits(const float* __restrict__ x,
                                                const float* __restrict__ w) {
    const int warp = threadIdx.x >> 5;
    const int lane = threadIdx.x & 31;
    const int row  = blockIdx.x * 8 + warp;

    const float4* xr = reinterpret_cast<const float4*>(x) + (size_t)row * (D / 4);
    const float4* w4 = reinterpret_cast<const float4*>(w);

    // register-free MLP: 8 outstanding prefetches per thread
#pragma unroll
    for (int k = 0; k < 8; k++)
        asm volatile("prefetch.global.L1 [%0];" :: "l"(xr + lane + 32 * k));

    float s = 0.f;
#pragma unroll
    for (int k = 0; k < 8; k++) {
        const float4 xv = xr[lane + 32 * k];
        const float4 wv = __ldg(&w4[lane + 32 * k]);
        s += xv.x * wv.x;
        s += xv.y * wv.y;
        s += xv.z * wv.z;
        s += xv.w * wv.w;
    }
#pragma unroll
    for (int off = 16; off; off >>= 1)
        s += __shfl_xor_sync(0xffffffffu, s, off);

    if (lane == 0) {
        float z = s, a;
        if (z >= 0.f) {
            a = 1.f / (1.f + expf(-z));
        } else {
            float e = expf(z);
            a = e / (1.f + e);
        }
        g_a[row] = a;
    }
}

// ---------------------------------------------------------------------------
// Kernel 2: b = cumsum(a) replicating jax.lax.associative_scan's fp32 tree,
// then derive per-column {idx, m, c} and the exact rowstart table.
// idx is non-decreasing with steps <= 1 (a_i < 1): crossing thread writes
// rowstart directly, no atomics, no search.  (Unchanged from R9.)
// ---------------------------------------------------------------------------
__global__ void k_scan() {
    __shared__ float sh[8192];
    const int tid = threadIdx.x;   // 1024 threads

    for (int i = tid; i < 4096; i += 1024)
        sh[i] = g_a[2 * i] + g_a[2 * i + 1];
    __syncthreads();
    for (int l = 2; l <= 7; l++) {                 // n = 2048 .. 64
        const int n    = N >> l;
        const int off  = 8192 - 2 * (8192 >> l);
        const int offp = 8192 - 2 * (8192 >> (l - 1));
        for (int i = tid; i < n; i += 1024)
            sh[off + i] = sh[offp + 2 * i] + sh[offp + 2 * i + 1];
        __syncthreads();
    }

    if (tid < 32) {
        for (int l = 8; l <= 13; l++) {
            const int n    = N >> l;
            const int off  = 8192 - 2 * (8192 >> l);
            const int offp = 8192 - 2 * (8192 >> (l - 1));
            if (tid < n)
                sh[off + tid] = sh[offp + 2 * tid] + sh[offp + 2 * tid + 1];
            __syncwarp();
        }
        for (int l = 12; l >= 8; l--) {
            const int n    = N >> l;
            const int off  = 8192 - 2 * (8192 >> l);
            const int offc = 8192 - 2 * (8192 >> (l + 1));
            float v = 0.f;
            if (tid < n) {
                if (tid & 1)       v = sh[offc + (tid >> 1)];
                else if (tid == 0) v = sh[off];
                else               v = sh[offc + (tid >> 1) - 1] + sh[off + tid];
            }
            __syncwarp();
            if (tid < n) sh[off + tid] = v;
            __syncwarp();
        }
    }
    __syncthreads();

    for (int l = 7; l >= 1; l--) {                 // n = 64 .. 4096, in place
        const int n    = N >> l;
        const int off  = 8192 - 2 * (8192 >> l);
        const int offc = 8192 - 2 * (8192 >> (l + 1));
        for (int i = tid; i < n; i += 1024) {
            float v;
            if (i & 1)       v = sh[offc + (i >> 1)];
            else if (i == 0) v = sh[off];
            else             v = sh[offc + (i >> 1) - 1] + sh[off + i];
            sh[off + i] = v;
        }
        __syncthreads();
    }

    int last_idx = 0;
    for (int i = tid; i < N; i += 1024) {
        const float ai = g_a[i];
        float bi;
        if (i == 0)      bi = ai;
        else if (i & 1)  bi = sh[i >> 1];
        else             bi = sh[(i >> 1) - 1] + ai;

        int prev;
        if (i == 0) {
            prev = 0;
        } else {
            const int k = i - 1;
            float bp;
            if (k == 0)      bp = g_a[0];
            else if (k & 1)  bp = sh[k >> 1];
            else             bp = sh[(k >> 1) - 1] + g_a[k];
            prev = (int)floorf(bp);
        }
        const int idx   = (int)floorf(bi);
        const bool same = (idx == prev);
        const float frac = bi - (float)idx;

        const float m = same ? ai : frac;
        const float c = same ? 0.f : (ai - frac);
        g_pack[i] = make_int4(idx, __float_as_int(m), __float_as_int(c), 0);

        if (i == 0) g_rowstart[0] = 0;
        else if (!same) g_rowstart[idx] = i;
        if (i == N - 1) last_idx = idx;
    }
    __syncthreads();

    __shared__ int s_last;
    if (tid == ((N - 1) & 1023)) s_last = last_idx;
    __syncthreads();
    for (int j = s_last + 1 + tid; j <= N + 1; j += 1024)
        g_rowstart[j] = N;
}

// ---------------------------------------------------------------------------
// Kernel 3: gather (R9 structure). One block per output row; span
// [rowstart[j], rowstart[j+2]); lane-parallel pack prefetch + shfl
// broadcast. NEW: skip threshold raised to 1e-5 (adds <=~1e-5 rel error
// against a 1e-3 tolerance; 5.5e-4 currently used) — skips ~36% of columns
// instead of ~19%.
// ---------------------------------------------------------------------------
__global__ void __launch_bounds__(256) k_gather(const float* __restrict__ x,
                                                float* __restrict__ out) {
    const int j = blockIdx.x;     // output row
    const int t = threadIdx.x;    // 0..255, float4 lanes
    const int lane = t & 31;

    const int s = __ldg(&g_rowstart[j]);
    const int e = __ldg(&g_rowstart[j + 2]);

    float4 acc = make_float4(0.f, 0.f, 0.f, 0.f);
    for (int base = s; base < e; base += 32) {
        float wl = 0.f;
        const int i = base + lane;
        if (i < e) {
            const int4 p = __ldg(&g_pack[i]);
            if (p.x == j)          wl = __int_as_float(p.y);   // m
            else if (p.x == j + 1) wl = __int_as_float(p.z);   // c
        }
        const int cnt = min(32, e - base);
#pragma unroll 4
        for (int k = 0; k < cnt; k++) {
            const float wk = __shfl_sync(0xffffffffu, wl, k);
            if (fabsf(wk) > 1e-5f) {    // warp-uniform; sub-tolerance skip
                const float4 v =
                    reinterpret_cast<const float4*>(x)[(size_t)(base + k) * (D / 4) + t];
                acc.x += wk * v.x;
                acc.y += wk * v.y;
                acc.z += wk * v.z;
                acc.w += wk * v.w;
            }
        }
    }
    reinterpret_cast<float4*>(out)[(size_t)j * (D / 4) + t] = acc;
}

// ---------------------------------------------------------------------------
extern "C" void kernel_launch(void* const* d_in, const int* in_sizes, int n_in,
                              void* d_out, int out_size) {
    const float* x = (const float*)d_in[0];   // [8192, 1024] f32
    const float* w = (const float*)d_in[1];   // [1024, 1]    f32
    float* out = (float*)d_out;               // [8192, 1024] f32

    k_logits<<<N / 8, 256>>>(x, w);
    k_scan<<<1, 1024>>>();
    k_gather<<<N, 256>>>(x, out);
}

// round 13
// speedup vs baseline: 1.0102x; 1.0102x over previous
#include <cuda_runtime.h>
#include <math.h>

#define N 8192
#define D 1024

// Scratch (allocation-free rule: __device__ globals)
__device__ float g_a[N];            // sigmoid(x @ w)
__device__ int4  g_pack[N];         // {idx, bits(m), bits(c), 0} per column
__device__ int   g_rowstart[N + 2]; // lower_bound(idx >= j), j in [0, N+1]

__device__ __forceinline__ unsigned smem_u32(const void* p) {
    unsigned r;
    asm("{ .reg .u64 t; cvta.to.shared.u64 t, %1; cvt.u32.u64 %0, t; }"
        : "=r"(r) : "l"(p));
    return r;
}

// ---------------------------------------------------------------------------
// Kernel 1: z = x @ w, a = sigmoid(z).  One warp per row. The 8 row chunks
// are fetched with per-thread cp.async.cg (register-free, truly async ->
// MLP=8 per thread, ~196KB outstanding/SM). Each thread copies exactly the
// float4s it consumes, so wait_group 0 gives own-thread visibility with no
// block sync. FFMA/shfl chain identical on identical values -> g_a bitwise
// unchanged.
// ---------------------------------------------------------------------------
__global__ void __launch_bounds__(256) k_logits(const float* __restrict__ x,
                                                const float* __restrict__ w) {
    __shared__ alignas(16) float sx[8 * D];        // 32 KB
    const int warp = threadIdx.x >> 5;
    const int lane = threadIdx.x & 31;
    const int row  = blockIdx.x * 8 + warp;

    const float4* xr = reinterpret_cast<const float4*>(x) + (size_t)row * (D / 4);
    const float4* w4 = reinterpret_cast<const float4*>(w);
    float4* sr = reinterpret_cast<float4*>(sx) + warp * (D / 4);

    // 8 genuinely-async 16B copies per thread (no destination register)
#pragma unroll
    for (int k = 0; k < 8; k++) {
        const unsigned dst = smem_u32(sr + lane + 32 * k);
        asm volatile("cp.async.cg.shared.global [%0], [%1], 16;"
                     :: "r"(dst), "l"(xr + lane + 32 * k) : "memory");
    }
    asm volatile("cp.async.commit_group;" ::: "memory");
    asm volatile("cp.async.wait_group 0;" ::: "memory");

    float s = 0.f;
#pragma unroll
    for (int k = 0; k < 8; k++) {
        const float4 xv = sr[lane + 32 * k];
        const float4 wv = __ldg(&w4[lane + 32 * k]);
        s += xv.x * wv.x;
        s += xv.y * wv.y;
        s += xv.z * wv.z;
        s += xv.w * wv.w;
    }
#pragma unroll
    for (int off = 16; off; off >>= 1)
        s += __shfl_xor_sync(0xffffffffu, s, off);

    if (lane == 0) {
        float z = s, a;
        if (z >= 0.f) {
            a = 1.f / (1.f + expf(-z));
        } else {
            float e = expf(z);
            a = e / (1.f + e);
        }
        g_a[row] = a;
    }
}

// ---------------------------------------------------------------------------
// Kernel 2: b = cumsum(a) replicating jax.lax.associative_scan's fp32 tree,
// then derive per-column {idx, m, c} and the exact rowstart table.
// (Unchanged from R9/R11 — validated.)
// ---------------------------------------------------------------------------
__global__ void k_scan() {
    __shared__ float sh[8192];
    const int tid = threadIdx.x;   // 1024 threads

    for (int i = tid; i < 4096; i += 1024)
        sh[i] = g_a[2 * i] + g_a[2 * i + 1];
    __syncthreads();
    for (int l = 2; l <= 7; l++) {                 // n = 2048 .. 64
        const int n    = N >> l;
        const int off  = 8192 - 2 * (8192 >> l);
        const int offp = 8192 - 2 * (8192 >> (l - 1));
        for (int i = tid; i < n; i += 1024)
            sh[off + i] = sh[offp + 2 * i] + sh[offp + 2 * i + 1];
        __syncthreads();
    }

    if (tid < 32) {
        for (int l = 8; l <= 13; l++) {
            const int n    = N >> l;
            const int off  = 8192 - 2 * (8192 >> l);
            const int offp = 8192 - 2 * (8192 >> (l - 1));
            if (tid < n)
                sh[off + tid] = sh[offp + 2 * tid] + sh[offp + 2 * tid + 1];
            __syncwarp();
        }
        for (int l = 12; l >= 8; l--) {
            const int n    = N >> l;
            const int off  = 8192 - 2 * (8192 >> l);
            const int offc = 8192 - 2 * (8192 >> (l + 1));
            float v = 0.f;
            if (tid < n) {
                if (tid & 1)       v = sh[offc + (tid >> 1)];
                else if (tid == 0) v = sh[off];
                else               v = sh[offc + (tid >> 1) - 1] + sh[off + tid];
            }
            __syncwarp();
            if (tid < n) sh[off + tid] = v;
            __syncwarp();
        }
    }
    __syncthreads();

    for (int l = 7; l >= 1; l--) {                 // n = 64 .. 4096, in place
        const int n    = N >> l;
        const int off  = 8192 - 2 * (8192 >> l);
        const int offc = 8192 - 2 * (8192 >> (l + 1));
        for (int i = tid; i < n; i += 1024) {
            float v;
            if (i & 1)       v = sh[offc + (i >> 1)];
            else if (i == 0) v = sh[off];
            else             v = sh[offc + (i >> 1) - 1] + sh[off + i];
            sh[off + i] = v;
        }
        __syncthreads();
    }

    int last_idx = 0;
    for (int i = tid; i < N; i += 1024) {
        const float ai = g_a[i];
        float bi;
        if (i == 0)      bi = ai;
        else if (i & 1)  bi = sh[i >> 1];
        else             bi = sh[(i >> 1) - 1] + ai;

        int prev;
        if (i == 0) {
            prev = 0;
        } else {
            const int k = i - 1;
            float bp;
            if (k == 0)      bp = g_a[0];
            else if (k & 1)  bp = sh[k >> 1];
            else             bp = sh[(k >> 1) - 1] + g_a[k];
            prev = (int)floorf(bp);
        }
        const int idx   = (int)floorf(bi);
        const bool same = (idx == prev);
        const float frac = bi - (float)idx;

        const float m = same ? ai : frac;
        const float c = same ? 0.f : (ai - frac);
        g_pack[i] = make_int4(idx, __float_as_int(m), __float_as_int(c), 0);

        if (i == 0) g_rowstart[0] = 0;
        else if (!same) g_rowstart[idx] = i;
        if (i == N - 1) last_idx = idx;
    }
    __syncthreads();

    __shared__ int s_last;
    if (tid == ((N - 1) & 1023)) s_last = last_idx;
    __syncthreads();
    for (int j = s_last + 1 + tid; j <= N + 1; j += 1024)
        g_rowstart[j] = N;
}

// ---------------------------------------------------------------------------
// Kernel 3: gather (exact R9/R11 — validated best). One block per output
// row; span [rowstart[j], rowstart[j+2]); lane-parallel pack prefetch +
// shfl broadcast; |w| <= 1e-12 contributions skipped.
// ---------------------------------------------------------------------------
__global__ void __launch_bounds__(256) k_gather(const float* __restrict__ x,
                                                float* __restrict__ out) {
    const int j = blockIdx.x;     // output row
    const int t = threadIdx.x;    // 0..255, float4 lanes
    const int lane = t & 31;

    const int s = __ldg(&g_rowstart[j]);
    const int e = __ldg(&g_rowstart[j + 2]);

    float4 acc = make_float4(0.f, 0.f, 0.f, 0.f);
    for (int base = s; base < e; base += 32) {
        float wl = 0.f;
        const int i = base + lane;
        if (i < e) {
            const int4 p = __ldg(&g_pack[i]);
            if (p.x == j)          wl = __int_as_float(p.y);   // m
            else if (p.x == j + 1) wl = __int_as_float(p.z);   // c
        }
        const int cnt = min(32, e - base);
#pragma unroll 4
        for (int k = 0; k < cnt; k++) {
            const float wk = __shfl_sync(0xffffffffu, wl, k);
            if (fabsf(wk) > 1e-12f) {   // warp-uniform; sub-tolerance skip
                const float4 v =
                    reinterpret_cast<const float4*>(x)[(size_t)(base + k) * (D / 4) + t];
                acc.x += wk * v.x;
                acc.y += wk * v.y;
                acc.z += wk * v.z;
                acc.w += wk * v.w;
            }
        }
    }
    reinterpret_cast<float4*>(out)[(size_t)j * (D / 4) + t] = acc;
}

// ---------------------------------------------------------------------------
extern "C" void kernel_launch(void* const* d_in, const int* in_sizes, int n_in,
                              void* d_out, int out_size) {
    const float* x = (const float*)d_in[0];   // [8192, 1024] f32
    const float* w = (const float*)d_in[1];   // [1024, 1]    f32
    float* out = (float*)d_out;               // [8192, 1024] f32

    k_logits<<<N / 8, 256>>>(x, w);
    k_scan<<<1, 1024>>>();
    k_gather<<<N, 256>>>(x, out);
}